// round 16
// baseline (speedup 1.0000x reference)
#include <cuda_runtime.h>
#include <cuda_fp16.h>

#define NFLAT 1056768   /* 32*256*129 */
#define PLANE_F 33024   /* 256*129 */
#define PIX 2097152     /* 32*256*256 per (b,c) plane */
#define NREAL 25165824  /* 12 * PIX */
#define NGRP 3          /* groups of 4 planes */
#define PACK_BLOCKS 6144   /* NGRP*PIX/4/256 */
#define H_BLOCKS 480       /* 15 (c,k2) x 32 i0 */
#define CHUNK 512

__device__ float2 d_H[8192 * 15];    // [i0*256+i1][c*5+k2]
__device__ uint4  d_quads[NGRP * PIX]; // per pixel: 4 planes' (v[x],v[x+1]) half2

__device__ __forceinline__ unsigned pk2(float a, float b) {
    __half2 h = __floats2half2_rn(a, b);
    return *reinterpret_cast<unsigned*>(&h);
}

// Blocks [0, H_BLOCKS): fold sparse spectrum into per-row H (staged feed).
// Blocks [H_BLOCKS, ...): pack fr 4-plane groups into staggered fp16 quads.
__global__ void __launch_bounds__(256) pack_h_kernel(
        const float* __restrict__ fr,
        const float* __restrict__ seeds,
        const float* __restrict__ Pk,
        const float* __restrict__ defscale,
        const int*  __restrict__ feed_idx,
        int fdim) {
    if (blockIdx.x < H_BLOCKS) {
        __shared__ float2 sW[256];
        __shared__ float sV[CHUNK];
        __shared__ int   sM[CHUNK];
        int tid = threadIdx.x;
        {
            float sn, cs;
            sincospif((float)tid * (1.0f / 128.0f), &sn, &cs);
            sW[tid] = make_float2(cs, sn);
        }
        int ex = blockIdx.x;
        int ck = ex >> 5;            // 0..14 = c*5+k2
        int i0 = ex & 31;
        int i1 = tid;
        int c  = ck / 5, k2 = ck - c * 5;
        float dsc = __ldg(defscale + c);
        const float inv_n = 1.0f / 2097152.0f;    // irfftn normalization
        float ax = 0.f, ay = 0.f;

        for (int base = 0; base < fdim; base += CHUNK) {
            int len = min(CHUNK, fdim - base);
            __syncthreads();
            for (int t = tid; t < len; t += 256) {
                int j = base + t;
                int flat = __ldg(feed_idx + j);
                int part = flat / NFLAT;              // 0 = re, 1 = im
                int r = flat - part * NFLAT;
                int k0 = r / PLANE_F; r -= k0 * PLANE_F;
                int k1 = r / 129;
                int k2e = r - k1 * 129;
                int f0 = (k0 <= 16) ? k0 : k0 - 32;   // |f0| <= 4 (ksq<=16)
                int f1 = (k1 <= 128) ? k1 : k1 - 256; // |f1| <= 4
                float w = (k0 == 0 && k1 == 0 && k2e == 0) ? 1.0f : 2.0f;
                float v = __ldg(Pk + j) * w * inv_n
                        * __ldg(seeds + c * fdim + j) * dsc;
                // part=1 (i * e^{it}) == phase rotation by +64/256 turn
                int tb = (8 * f0 * i0 + 64 * part + 8192) & 255;
                sV[t] = (k2e == k2) ? v : 0.0f;       // mask wrong-k2 entries
                sM[t] = (tb << 8) | (f1 + 4);
            }
            __syncthreads();
            for (int t = 0; t < len; t++) {
                int m = sM[t];
                float v = sV[t];
                int tt = ((m >> 8) + ((m & 15) - 4) * i1) & 255;
                float2 wv = sW[tt];
                ax += v * wv.x;
                ay += v * wv.y;
            }
        }
        d_H[(i0 * 256 + i1) * 15 + ck] = make_float2(ax, ay);
    } else {
        int t = (blockIdx.x - H_BLOCKS) * 256 + threadIdx.x;
        int i = t * 4;                       // 4 consecutive pixels
        int grp = i >> 21;                   // plane group (PIX = 2^21)
        int pix = i & (PIX - 1);
        int pos = pix & 255;
        float a[4][5];
        #pragma unroll
        for (int p = 0; p < 4; p++) {
            const float* pp = fr + (size_t)(4 * grp + p) * PIX;
            float4 f = __ldcs(reinterpret_cast<const float4*>(pp + pix));
            float s = __ldcs(pp + min(pix + 4, PIX - 1));
            a[p][0] = f.x; a[p][1] = f.y; a[p][2] = f.z; a[p][3] = f.w;
            a[p][4] = (pos == 252) ? f.w : s;   // clamp x-pair at row end
        }
        uint4* dst = d_quads + ((size_t)grp << 21) + pix;
        #pragma unroll
        for (int j = 0; j < 4; j++) {
            uint4 o;
            o.x = pk2(a[0][j], a[0][j+1]);
            o.y = pk2(a[1][j], a[1][j+1]);
            o.z = pk2(a[2][j], a[2][j+1]);
            o.w = pk2(a[3][j], a[3][j+1]);
            dst[j] = o;
        }
    }
}

// Barrier-free, smem-free deform: uniform H -> disp -> 12 LDG.128 gathers,
// packed HFMA2 interpolation (weights folded into 4 shared half2 vectors).
__global__ void __launch_bounds__(256, 8) deform_kernel(float* __restrict__ out) {
    int i2 = threadIdx.x;
    int i1 = blockIdx.x;
    int i0 = blockIdx.y;

    float s1, c1;
    sincospif((float)i2 * (1.0f / 128.0f), &s1, &c1);
    float2 w1 = make_float2(c1, s1);
    float2 w2 = make_float2(c1 * c1 - s1 * s1, 2.f * c1 * s1);
    float2 w3 = make_float2(w2.x * w1.x - w2.y * w1.y, w2.x * w1.y + w2.y * w1.x);
    float2 w4 = make_float2(w2.x * w2.x - w2.y * w2.y, 2.f * w2.x * w2.y);

    const float2* Hp = d_H + (i0 * 256 + i1) * 15;
    float dd[3];
    #pragma unroll
    for (int c = 0; c < 3; c++) {
        float2 h0 = __ldg(Hp + c * 5 + 0);
        float2 h1 = __ldg(Hp + c * 5 + 1);
        float2 h2 = __ldg(Hp + c * 5 + 2);
        float2 h3 = __ldg(Hp + c * 5 + 3);
        float2 h4 = __ldg(Hp + c * 5 + 4);
        float acc = h0.x;                          // k2=0: w=(1,0)
        acc += h1.x * w1.x - h1.y * w1.y;
        acc += h2.x * w2.x - h2.y * w2.y;
        acc += h3.x * w3.x - h3.y * w3.y;
        acc += h4.x * w4.x - h4.y * w4.y;
        dd[c] = acc;
    }

    // grid_sample: bilinear, border clamp, align_corners=True -> sample at i - disp
    float fz = fminf(fmaxf((float)i0 - dd[0], 0.f), 31.f);
    float fy = fminf(fmaxf((float)i1 - dd[1], 0.f), 255.f);
    float fx = fminf(fmaxf((float)i2 - dd[2], 0.f), 255.f);
    int z0 = (int)fz, y0 = (int)fy, x0 = (int)fx;
    float wz = fz - (float)z0, wy = fy - (float)y0, wx = fx - (float)x0;
    int z1 = min(z0 + 1, 31), y1 = min(y0 + 1, 255);

    int q00 = z0 * 65536 + y0 * 256 + x0;
    int q01 = z0 * 65536 + y1 * 256 + x0;
    int q10 = z1 * 65536 + y0 * 256 + x0;
    int q11 = z1 * 65536 + y1 * 256 + x0;
    int pix = i0 * 65536 + i1 * 256 + i2;

    float iwx = 1.f - wx, iwy = 1.f - wy, iwz = 1.f - wz;
    // tap weights: q00=iwy*iwz, q01=wy*iwz, q10=iwy*wz, q11=wy*wz,
    // folded with (iwx, wx) into half2 lanes (shared across all 12 planes)
    float w00 = iwy * iwz, w01 = wy * iwz, w10 = iwy * wz, w11 = wy * wz;
    __half2 W00 = __floats2half2_rn(w00 * iwx, w00 * wx);
    __half2 W01 = __floats2half2_rn(w01 * iwx, w01 * wx);
    __half2 W10 = __floats2half2_rn(w10 * iwx, w10 * wx);
    __half2 W11 = __floats2half2_rn(w11 * iwx, w11 * wx);

    #pragma unroll
    for (int grp = 0; grp < NGRP; grp++) {
        const uint4* p = d_quads + ((size_t)grp << 21);
        uint4 v0 = __ldg(p + q00);
        uint4 v1 = __ldg(p + q01);
        uint4 v2 = __ldg(p + q10);
        uint4 v3 = __ldg(p + q11);
        unsigned s0[4] = {v0.x, v0.y, v0.z, v0.w};
        unsigned s1v[4] = {v1.x, v1.y, v1.z, v1.w};
        unsigned s2v[4] = {v2.x, v2.y, v2.z, v2.w};
        unsigned s3v[4] = {v3.x, v3.y, v3.z, v3.w};
        #pragma unroll
        for (int s = 0; s < 4; s++) {
            __half2 acc = __hmul2(*reinterpret_cast<__half2*>(&s0[s]), W00);
            acc = __hfma2(*reinterpret_cast<__half2*>(&s1v[s]), W01, acc);
            acc = __hfma2(*reinterpret_cast<__half2*>(&s2v[s]), W10, acc);
            acc = __hfma2(*reinterpret_cast<__half2*>(&s3v[s]), W11, acc);
            float res = __low2float(acc) + __high2float(acc);
            __stcs(out + (size_t)(4 * grp + s) * PIX + pix, res);
        }
    }
}

extern "C" void kernel_launch(void* const* d_in, const int* in_sizes, int n_in,
                              void* d_out, int out_size) {
    const float* fr       = (const float*)d_in[0];
    const float* seeds    = (const float*)d_in[1];
    const float* Pk       = (const float*)d_in[2];
    const float* defscale = (const float*)d_in[3];
    const int*   feed_idx = (const int*)d_in[5];
    int fdim = in_sizes[5];

    pack_h_kernel<<<H_BLOCKS + PACK_BLOCKS, 256>>>(fr, seeds, Pk, defscale, feed_idx, fdim);
    dim3 g(256, 32);
    deform_kernel<<<g, 256>>>((float*)d_out);
}

// round 17
// speedup vs baseline: 1.0134x; 1.0134x over previous
#include <cuda_runtime.h>
#include <cuda_fp16.h>

#define NFLAT 1056768   /* 32*256*129 */
#define PLANE_F 33024   /* 256*129 */
#define PIX 2097152     /* 32*256*256 per (b,c) plane */
#define NREAL 25165824  /* 12 * PIX */
#define NPAIR 6         /* plane pairs */
#define PACK_BLOCKS 6144   /* NPAIR*PIX/8/256 */
#define H_BLOCKS 480       /* 15 (c,k2) x 32 i0 */
#define CHUNK 512

__device__ float2  d_H[8192 * 15];     // [i0*256+i1][c*5+k2]
__device__ uint2   d_quads[NPAIR * PIX]; // (pa[x],pa[x+1],pb[x],pb[x+1]) fp16 quads

__device__ __forceinline__ unsigned pk2(float a, float b) {
    __half2 h = __floats2half2_rn(a, b);
    return *reinterpret_cast<unsigned*>(&h);
}

// Blocks [0, H_BLOCKS): fold sparse spectrum into per-row H (staged feed).
// Blocks [H_BLOCKS, ...): pack fr plane-pairs into staggered fp16 quads,
// 8 pixels per thread (4 independent float4 loads in flight -> latency hidden).
__global__ void __launch_bounds__(256) pack_h_kernel(
        const float* __restrict__ fr,
        const float* __restrict__ seeds,
        const float* __restrict__ Pk,
        const float* __restrict__ defscale,
        const int*  __restrict__ feed_idx,
        int fdim) {
    if (blockIdx.x < H_BLOCKS) {
        __shared__ float2 sW[256];
        __shared__ float sV[CHUNK];
        __shared__ int   sM[CHUNK];
        int tid = threadIdx.x;
        {
            float sn, cs;
            sincospif((float)tid * (1.0f / 128.0f), &sn, &cs);
            sW[tid] = make_float2(cs, sn);
        }
        int ex = blockIdx.x;
        int ck = ex >> 5;            // 0..14 = c*5+k2
        int i0 = ex & 31;
        int i1 = tid;
        int c  = ck / 5, k2 = ck - c * 5;
        float dsc = __ldg(defscale + c);
        const float inv_n = 1.0f / 2097152.0f;    // irfftn normalization
        float ax = 0.f, ay = 0.f;

        for (int base = 0; base < fdim; base += CHUNK) {
            int len = min(CHUNK, fdim - base);
            __syncthreads();
            for (int t = tid; t < len; t += 256) {
                int j = base + t;
                int flat = __ldg(feed_idx + j);
                int part = flat / NFLAT;              // 0 = re, 1 = im
                int r = flat - part * NFLAT;
                int k0 = r / PLANE_F; r -= k0 * PLANE_F;
                int k1 = r / 129;
                int k2e = r - k1 * 129;
                int f0 = (k0 <= 16) ? k0 : k0 - 32;   // |f0| <= 4 (ksq<=16)
                int f1 = (k1 <= 128) ? k1 : k1 - 256; // |f1| <= 4
                float w = (k0 == 0 && k1 == 0 && k2e == 0) ? 1.0f : 2.0f;
                float v = __ldg(Pk + j) * w * inv_n
                        * __ldg(seeds + c * fdim + j) * dsc;
                // part=1 (i * e^{it}) == phase rotation by +64/256 turn
                int tb = (8 * f0 * i0 + 64 * part + 8192) & 255;
                sV[t] = (k2e == k2) ? v : 0.0f;       // mask wrong-k2 entries
                sM[t] = (tb << 8) | (f1 + 4);
            }
            __syncthreads();
            for (int t = 0; t < len; t++) {
                int m = sM[t];
                float v = sV[t];
                int tt = ((m >> 8) + ((m & 15) - 4) * i1) & 255;
                float2 wv = sW[tt];
                ax += v * wv.x;
                ay += v * wv.y;
            }
        }
        d_H[(i0 * 256 + i1) * 15 + ck] = make_float2(ax, ay);
    } else {
        int t = (blockIdx.x - H_BLOCKS) * 256 + threadIdx.x;
        int i = t * 8;                       // 8 consecutive pixels of one pair
        int g = i >> 21;                     // pair id (PIX = 2^21)
        int pix = i & (PIX - 1);
        const float* pa = fr + (size_t)(2 * g) * PIX;
        const float* pb = pa + PIX;
        // issue all 6 loads before any use
        float4 fa0 = __ldcs(reinterpret_cast<const float4*>(pa + pix));
        float4 fa1 = __ldcs(reinterpret_cast<const float4*>(pa + pix + 4));
        float4 fb0 = __ldcs(reinterpret_cast<const float4*>(pb + pix));
        float4 fb1 = __ldcs(reinterpret_cast<const float4*>(pb + pix + 4));
        int nn = min(pix + 8, PIX - 1);
        float sa = __ldcs(pa + nn);
        float sb = __ldcs(pb + nn);
        int pos = pix & 255;
        float a[9] = {fa0.x, fa0.y, fa0.z, fa0.w, fa1.x, fa1.y, fa1.z, fa1.w,
                      (pos == 248) ? fa1.w : sa};   // clamp x-pair at row end
        float b[9] = {fb0.x, fb0.y, fb0.z, fb0.w, fb1.x, fb1.y, fb1.z, fb1.w,
                      (pos == 248) ? fb1.w : sb};
        uint4* dst = reinterpret_cast<uint4*>(d_quads + ((size_t)g << 21) + pix);
        #pragma unroll
        for (int j = 0; j < 4; j++) {
            uint4 o;
            o.x = pk2(a[2*j],   a[2*j+1]);
            o.y = pk2(b[2*j],   b[2*j+1]);
            o.z = pk2(a[2*j+1], a[2*j+2]);
            o.w = pk2(b[2*j+1], b[2*j+2]);
            dst[j] = o;
        }
    }
}

// Barrier-free, smem-free deform (R15 champion): uniform H -> disp ->
// 24 LDG.64 quad gathers in 3 chunks of 2 pairs, fp32 interpolation.
__global__ void __launch_bounds__(256, 8) deform_kernel(float* __restrict__ out) {
    int i2 = threadIdx.x;
    int i1 = blockIdx.x;
    int i0 = blockIdx.y;

    float s1, c1;
    sincospif((float)i2 * (1.0f / 128.0f), &s1, &c1);
    float2 w1 = make_float2(c1, s1);
    float2 w2 = make_float2(c1 * c1 - s1 * s1, 2.f * c1 * s1);
    float2 w3 = make_float2(w2.x * w1.x - w2.y * w1.y, w2.x * w1.y + w2.y * w1.x);
    float2 w4 = make_float2(w2.x * w2.x - w2.y * w2.y, 2.f * w2.x * w2.y);

    const float2* Hp = d_H + (i0 * 256 + i1) * 15;
    float dd[3];
    #pragma unroll
    for (int c = 0; c < 3; c++) {
        float2 h0 = __ldg(Hp + c * 5 + 0);
        float2 h1 = __ldg(Hp + c * 5 + 1);
        float2 h2 = __ldg(Hp + c * 5 + 2);
        float2 h3 = __ldg(Hp + c * 5 + 3);
        float2 h4 = __ldg(Hp + c * 5 + 4);
        float acc = h0.x;                          // k2=0: w=(1,0)
        acc += h1.x * w1.x - h1.y * w1.y;
        acc += h2.x * w2.x - h2.y * w2.y;
        acc += h3.x * w3.x - h3.y * w3.y;
        acc += h4.x * w4.x - h4.y * w4.y;
        dd[c] = acc;
    }

    // grid_sample: bilinear, border clamp, align_corners=True -> sample at i - disp
    float fz = fminf(fmaxf((float)i0 - dd[0], 0.f), 31.f);
    float fy = fminf(fmaxf((float)i1 - dd[1], 0.f), 255.f);
    float fx = fminf(fmaxf((float)i2 - dd[2], 0.f), 255.f);
    int z0 = (int)fz, y0 = (int)fy, x0 = (int)fx;
    float wz = fz - (float)z0, wy = fy - (float)y0, wx = fx - (float)x0;
    int z1 = min(z0 + 1, 31), y1 = min(y0 + 1, 255);

    // quads already encode x1 = min(x0+1,255)
    int q00 = z0 * 65536 + y0 * 256 + x0;
    int q01 = z0 * 65536 + y1 * 256 + x0;
    int q10 = z1 * 65536 + y0 * 256 + x0;
    int q11 = z1 * 65536 + y1 * 256 + x0;
    int pix = i0 * 65536 + i1 * 256 + i2;

    float iwx = 1.f - wx, iwy = 1.f - wy, iwz = 1.f - wz;

    #pragma unroll
    for (int gg = 0; gg < 3; gg++) {
        uint2 v[8];
        #pragma unroll
        for (int b = 0; b < 2; b++) {
            const uint2* p = d_quads + ((size_t)(2 * gg + b) << 21);
            v[b*4+0] = __ldg(p + q00);
            v[b*4+1] = __ldg(p + q01);
            v[b*4+2] = __ldg(p + q10);
            v[b*4+3] = __ldg(p + q11);
        }
        #pragma unroll
        for (int b = 0; b < 2; b++) {
            int g = 2 * gg + b;
            float2 a00 = __half22float2(*reinterpret_cast<__half2*>(&v[b*4+0].x));
            float2 a01 = __half22float2(*reinterpret_cast<__half2*>(&v[b*4+1].x));
            float2 a10 = __half22float2(*reinterpret_cast<__half2*>(&v[b*4+2].x));
            float2 a11 = __half22float2(*reinterpret_cast<__half2*>(&v[b*4+3].x));
            float c00 = a00.x * iwx + a00.y * wx;
            float c01 = a01.x * iwx + a01.y * wx;
            float c10 = a10.x * iwx + a10.y * wx;
            float c11 = a11.x * iwx + a11.y * wx;
            float ra = (c00 * iwy + c01 * wy) * iwz + (c10 * iwy + c11 * wy) * wz;

            float2 b00 = __half22float2(*reinterpret_cast<__half2*>(&v[b*4+0].y));
            float2 b01 = __half22float2(*reinterpret_cast<__half2*>(&v[b*4+1].y));
            float2 b10 = __half22float2(*reinterpret_cast<__half2*>(&v[b*4+2].y));
            float2 b11 = __half22float2(*reinterpret_cast<__half2*>(&v[b*4+3].y));
            c00 = b00.x * iwx + b00.y * wx;
            c01 = b01.x * iwx + b01.y * wx;
            c10 = b10.x * iwx + b10.y * wx;
            c11 = b11.x * iwx + b11.y * wx;
            float rb = (c00 * iwy + c01 * wy) * iwz + (c10 * iwy + c11 * wy) * wz;

            __stcs(out + (size_t)(2 * g) * PIX + pix, ra);
            __stcs(out + (size_t)(2 * g + 1) * PIX + pix, rb);
        }
    }
}

extern "C" void kernel_launch(void* const* d_in, const int* in_sizes, int n_in,
                              void* d_out, int out_size) {
    const float* fr       = (const float*)d_in[0];
    const float* seeds    = (const float*)d_in[1];
    const float* Pk       = (const float*)d_in[2];
    const float* defscale = (const float*)d_in[3];
    const int*   feed_idx = (const int*)d_in[5];
    int fdim = in_sizes[5];

    pack_h_kernel<<<H_BLOCKS + PACK_BLOCKS, 256>>>(fr, seeds, Pk, defscale, feed_idx, fdim);
    dim3 g(256, 32);
    deform_kernel<<<g, 256>>>((float*)d_out);
}